// round 6
// baseline (speedup 1.0000x reference)
#include <cuda_runtime.h>

#define NN 200000
#define DD 64
#define EE 600000
#define TE 1200000           // 2*EE directed edges after symmetrization
#define NBLK 196             // ceil(NN / 1024) build blocks

// Scratch: __device__ globals (no allocation allowed anywhere).
__device__ float g_xn[(size_t)NN * DD];    // l2-normalized x
__device__ float g_x1[(size_t)NN * DD];    // layer-1 output
__device__ int   g_cnt[NN];                // in-degree
__device__ int   g_off[NN];                // CSR bucket start
__device__ int   g_cur[NN];                // fill cursors
__device__ int   g_total;                  // global bucket cursor
__device__ int2  g_csr[TE];                // CSR slot: {src, __float_as_int(w)}

// ---------------------------------------------------------------------------
// Degree histogram: one thread per directed edge.
// Edge e: src = ei[e]; dst = ei[e+EE] for e<EE, ei[e-EE] for e>=EE.
__global__ void k_count(const int* __restrict__ ei) {
    int e = blockIdx.x * blockDim.x + threadIdx.x;
    if (e >= TE) return;
    int dst = (e < EE) ? ei[e + EE] : ei[e - EE];
    if ((unsigned)dst < (unsigned)NN) atomicAdd(&g_cnt[dst], 1);
}

// ---------------------------------------------------------------------------
// Bucket allocation: each block scans 1024 counts, grabs a contiguous range
// from g_total with ONE atomic, writes off/cur. Bucket order across blocks is
// nondeterministic but irrelevant (only placement permutes, not content).
__global__ void k_build_off() {
    __shared__ int sh[256];
    __shared__ int base_sh;
    int t = threadIdx.x;
    int b = blockIdx.x * 1024 + t * 4;
    int v0 = (b + 0 < NN) ? g_cnt[b + 0] : 0;
    int v1 = (b + 1 < NN) ? g_cnt[b + 1] : 0;
    int v2 = (b + 2 < NN) ? g_cnt[b + 2] : 0;
    int v3 = (b + 3 < NN) ? g_cnt[b + 3] : 0;
    int s = v0 + v1 + v2 + v3;
    sh[t] = s;
    __syncthreads();
    #pragma unroll
    for (int o = 1; o < 256; o <<= 1) {
        int x = (t >= o) ? sh[t - o] : 0;
        __syncthreads();
        sh[t] += x;
        __syncthreads();
    }
    if (t == 255) base_sh = atomicAdd(&g_total, sh[255]);
    __syncthreads();
    int excl = base_sh + sh[t] - s;
    if (b + 0 < NN) { g_off[b + 0] = excl;                g_cur[b + 0] = excl; }
    if (b + 1 < NN) { g_off[b + 1] = excl + v0;           g_cur[b + 1] = excl + v0; }
    if (b + 2 < NN) { g_off[b + 2] = excl + v0 + v1;      g_cur[b + 2] = excl + v0 + v1; }
    if (b + 3 < NN) { g_off[b + 3] = excl + v0 + v1 + v2; g_cur[b + 3] = excl + v0 + v1 + v2; }
}

// ---------------------------------------------------------------------------
// CSR fill: place {src, w} pair into dst's bucket (one STG.64).
__global__ void k_fill(const int* __restrict__ ei, const float* __restrict__ w) {
    int e = blockIdx.x * blockDim.x + threadIdx.x;
    if (e >= TE) return;
    int src = ei[e];
    int dst = (e < EE) ? ei[e + EE] : ei[e - EE];
    if ((unsigned)src >= (unsigned)NN || (unsigned)dst >= (unsigned)NN) return;
    int pos = atomicAdd(&g_cur[dst], 1);
    g_csr[pos] = make_int2(src, __float_as_int(w[e]));
}

// ---------------------------------------------------------------------------
// Row-wise L2 normalize: one warp covers 2 rows; each half-warp (16 lanes)
// does one row with float4 per lane (16*16B = 256B = full row).
__global__ void k_norm(const float* __restrict__ x) {
    int warp = threadIdx.x >> 5;
    int lane = threadIdx.x & 31;
    int h    = lane >> 4;          // which row within the warp's pair
    int f    = lane & 15;          // feature group
    int row  = blockIdx.x * 16 + warp * 2 + h;
    if (row >= NN) return;
    const float4 v = *(const float4*)(x + (size_t)row * DD + f * 4);
    float s = v.x * v.x + v.y * v.y + v.z * v.z + v.w * v.w;
    #pragma unroll
    for (int o = 8; o; o >>= 1) s += __shfl_xor_sync(0xffffffffu, s, o);
    float inv = 1.0f / fmaxf(sqrtf(s), 1e-12f);
    *(float4*)(g_xn + (size_t)row * DD + f * 4) =
        make_float4(v.x * inv, v.y * inv, v.z * inv, v.w * inv);
}

// ---------------------------------------------------------------------------
// Pull conv: one warp per dst row. Lanes = 16 features (float4) x 2 edge
// parity; two neighbor rows in flight per iteration. Atomic-free.
// Fused epilogue: leaky(acc/deg); FINAL adds xn + x1 and writes d_out.
template <bool FINAL>
__global__ void k_gather(const float* __restrict__ xin, float* __restrict__ xout) {
    int row  = blockIdx.x * 8 + (threadIdx.x >> 5);
    if (row >= NN) return;
    int lane = threadIdx.x & 31;
    int f = lane & 15;             // feature group: float4 at f*4
    int h = lane >> 4;             // edge parity 0/1
    int start = g_off[row];
    int cnt   = g_cnt[row];
    int end   = start + cnt;
    float4 acc = make_float4(0.f, 0.f, 0.f, 0.f);
    for (int e = start + h; e < end; e += 2) {
        int2  pr = __ldg(&g_csr[e]);          // broadcast within half-warp
        float wj = __int_as_float(pr.y);
        const float4 v = *(const float4*)(xin + (size_t)pr.x * DD + f * 4);
        acc.x += wj * v.x;
        acc.y += wj * v.y;
        acc.z += wj * v.z;
        acc.w += wj * v.w;
    }
    // combine the two edge-parity halves (feature f lives at lane f and f+16)
    acc.x += __shfl_xor_sync(0xffffffffu, acc.x, 16);
    acc.y += __shfl_xor_sync(0xffffffffu, acc.y, 16);
    acc.z += __shfl_xor_sync(0xffffffffu, acc.z, 16);
    acc.w += __shfl_xor_sync(0xffffffffu, acc.w, 16);
    if (h == 0) {
        float sc = 1.0f / fmaxf((float)cnt, 1.0f);
        acc.x *= sc; acc.y *= sc; acc.z *= sc; acc.w *= sc;
        acc.x = acc.x >= 0.f ? acc.x : 0.01f * acc.x;
        acc.y = acc.y >= 0.f ? acc.y : 0.01f * acc.y;
        acc.z = acc.z >= 0.f ? acc.z : 0.01f * acc.z;
        acc.w = acc.w >= 0.f ? acc.w : 0.01f * acc.w;
        size_t o = (size_t)row * DD + f * 4;
        if (FINAL) {
            float4 xn = *(const float4*)(g_xn + o);
            float4 x1 = *(const float4*)(g_x1 + o);
            acc.x += xn.x + x1.x;
            acc.y += xn.y + x1.y;
            acc.z += xn.z + x1.z;
            acc.w += xn.w + x1.w;
        }
        *(float4*)(xout + o) = acc;
    }
}

// ---------------------------------------------------------------------------
extern "C" void kernel_launch(void* const* d_in, const int* in_sizes, int n_in,
                              void* d_out, int out_size) {
    const float* emb = (const float*)d_in[0];   // [NN, DD] float32
    const int*   ei  = (const int*)d_in[1];     // [2, EE] int32
    const float* w   = (const float*)d_in[2];   // [TE, 1] float32
    float* out = (float*)d_out;

    void *p_cnt, *p_tot, *p_xn, *p_x1;
    cudaGetSymbolAddress(&p_cnt, g_cnt);
    cudaGetSymbolAddress(&p_tot, g_total);
    cudaGetSymbolAddress(&p_xn,  g_xn);
    cudaGetSymbolAddress(&p_x1,  g_x1);

    const int THR = 256;

    // CSR build: degrees -> bucket alloc -> fill
    cudaMemsetAsync(p_cnt, 0, NN * sizeof(int));
    cudaMemsetAsync(p_tot, 0, sizeof(int));
    k_count<<<(TE + THR - 1) / THR, THR>>>(ei);
    k_build_off<<<NBLK, THR>>>();
    k_fill<<<(TE + THR - 1) / THR, THR>>>(ei, w);

    // x = l2norm(emb)
    k_norm<<<(NN + 15) / 16, THR>>>(emb);

    // layer 1: x1 = leaky(gather(xn)/deg)            (fused epilogue)
    k_gather<false><<<(NN + 7) / 8, THR>>>((const float*)p_xn, (float*)p_x1);
    // layer 2: out = xn + x1 + leaky(gather(x1)/deg) (fused epilogue)
    k_gather<true><<<(NN + 7) / 8, THR>>>((const float*)p_x1, out);
}

// round 7
// speedup vs baseline: 1.0773x; 1.0773x over previous
#include <cuda_runtime.h>

#define NN 200000
#define DD 64
#define EE 600000
#define TE 1200000           // 2*EE directed edges after symmetrization
#define NBLK 196             // ceil(NN / 1024) build blocks

// Scratch: __device__ globals (no allocation allowed anywhere).
__device__ float g_xn[(size_t)NN * DD];    // l2-normalized x
__device__ float g_x1[(size_t)NN * DD];    // layer-1 output
__device__ int   g_cnt[NN];                // in-degree
__device__ int   g_off[NN];                // CSR bucket start
__device__ int   g_cur[NN];                // fill cursors
__device__ int   g_total;                  // global bucket cursor
__device__ int2  g_csr[TE];                // CSR slot: {src, __float_as_int(w)}

// ---------------------------------------------------------------------------
// Degree histogram: one thread per directed edge.
// Edge e: src = ei[e]; dst = ei[e+EE] for e<EE, ei[e-EE] for e>=EE.
__global__ void k_count(const int* __restrict__ ei) {
    int e = blockIdx.x * blockDim.x + threadIdx.x;
    if (e >= TE) return;
    int dst = (e < EE) ? ei[e + EE] : ei[e - EE];
    if ((unsigned)dst < (unsigned)NN) atomicAdd(&g_cnt[dst], 1);
}

// ---------------------------------------------------------------------------
// Bucket allocation: each block scans 1024 counts, grabs a contiguous range
// from g_total with ONE atomic, writes off/cur. Bucket placement order across
// blocks is nondeterministic but irrelevant (content per bucket is fixed).
__global__ void k_build_off() {
    __shared__ int sh[256];
    __shared__ int base_sh;
    int t = threadIdx.x;
    int b = blockIdx.x * 1024 + t * 4;
    int v0 = (b + 0 < NN) ? g_cnt[b + 0] : 0;
    int v1 = (b + 1 < NN) ? g_cnt[b + 1] : 0;
    int v2 = (b + 2 < NN) ? g_cnt[b + 2] : 0;
    int v3 = (b + 3 < NN) ? g_cnt[b + 3] : 0;
    int s = v0 + v1 + v2 + v3;
    sh[t] = s;
    __syncthreads();
    #pragma unroll
    for (int o = 1; o < 256; o <<= 1) {
        int x = (t >= o) ? sh[t - o] : 0;
        __syncthreads();
        sh[t] += x;
        __syncthreads();
    }
    if (t == 255) base_sh = atomicAdd(&g_total, sh[255]);
    __syncthreads();
    int excl = base_sh + sh[t] - s;
    if (b + 0 < NN) { g_off[b + 0] = excl;                g_cur[b + 0] = excl; }
    if (b + 1 < NN) { g_off[b + 1] = excl + v0;           g_cur[b + 1] = excl + v0; }
    if (b + 2 < NN) { g_off[b + 2] = excl + v0 + v1;      g_cur[b + 2] = excl + v0 + v1; }
    if (b + 3 < NN) { g_off[b + 3] = excl + v0 + v1 + v2; g_cur[b + 3] = excl + v0 + v1 + v2; }
}

// ---------------------------------------------------------------------------
// CSR fill: place {src, w} pair into dst's bucket (one STG.64).
__global__ void k_fill(const int* __restrict__ ei, const float* __restrict__ w) {
    int e = blockIdx.x * blockDim.x + threadIdx.x;
    if (e >= TE) return;
    int src = ei[e];
    int dst = (e < EE) ? ei[e + EE] : ei[e - EE];
    if ((unsigned)src >= (unsigned)NN || (unsigned)dst >= (unsigned)NN) return;
    int pos = atomicAdd(&g_cur[dst], 1);
    g_csr[pos] = make_int2(src, __float_as_int(w[e]));
}

// ---------------------------------------------------------------------------
// Row-wise L2 normalize: one warp covers 2 rows; each half-warp (16 lanes)
// does one row with float4 per lane (16*16B = 256B = full row).
__global__ void k_norm(const float* __restrict__ x) {
    int warp = threadIdx.x >> 5;
    int lane = threadIdx.x & 31;
    int h    = lane >> 4;          // which row within the warp's pair
    int f    = lane & 15;          // feature group
    int row  = blockIdx.x * 16 + warp * 2 + h;
    if (row >= NN) return;
    const float4 v = *(const float4*)(x + (size_t)row * DD + f * 4);
    float s = v.x * v.x + v.y * v.y + v.z * v.z + v.w * v.w;
    #pragma unroll
    for (int o = 8; o; o >>= 1) s += __shfl_xor_sync(0xffffffffu, s, o);
    float inv = 1.0f / fmaxf(sqrtf(s), 1e-12f);
    *(float4*)(g_xn + (size_t)row * DD + f * 4) =
        make_float4(v.x * inv, v.y * inv, v.z * inv, v.w * inv);
}

// ---------------------------------------------------------------------------
// Pull conv (R2 shape + unroll): one warp per dst row, float2 per lane.
// Coalesced 32-edge batch preload of {src,w}; inner loop shfl-broadcasts each
// edge; #pragma unroll 8 lets ptxas front-batch 8 independent shfl+LDG pairs
// (MLP~8 instead of ~1). Atomic-free; fused epilogue.
template <bool FINAL>
__global__ void k_gather(const float* __restrict__ xin, float* __restrict__ xout) {
    int row  = blockIdx.x * 8 + (threadIdx.x >> 5);
    if (row >= NN) return;
    int lane = threadIdx.x & 31;
    int start = __ldg(&g_off[row]);
    int cnt   = __ldg(&g_cnt[row]);
    float2 acc = make_float2(0.f, 0.f);
    for (int b = 0; b < cnt; b += 32) {
        int idx = b + lane;
        int2 pr = (idx < cnt) ? __ldg(&g_csr[start + idx]) : make_int2(0, 0);
        int m = min(32, cnt - b);
        #pragma unroll 8
        for (int j = 0; j < m; j++) {
            int   sj = __shfl_sync(0xffffffffu, pr.x, j);
            float wj = __int_as_float(__shfl_sync(0xffffffffu, pr.y, j));
            const float2 v = *(const float2*)(xin + (size_t)sj * DD + lane * 2);
            acc.x += wj * v.x;
            acc.y += wj * v.y;
        }
    }
    float sc = 1.0f / fmaxf((float)cnt, 1.0f);
    acc.x *= sc; acc.y *= sc;
    acc.x = acc.x >= 0.f ? acc.x : 0.01f * acc.x;
    acc.y = acc.y >= 0.f ? acc.y : 0.01f * acc.y;
    size_t o = (size_t)row * DD + lane * 2;
    if (FINAL) {
        float2 xn = *(const float2*)(g_xn + o);
        float2 x1 = *(const float2*)(g_x1 + o);
        acc.x += xn.x + x1.x;
        acc.y += xn.y + x1.y;
    }
    *(float2*)(xout + o) = acc;
}

// ---------------------------------------------------------------------------
extern "C" void kernel_launch(void* const* d_in, const int* in_sizes, int n_in,
                              void* d_out, int out_size) {
    const float* emb = (const float*)d_in[0];   // [NN, DD] float32
    const int*   ei  = (const int*)d_in[1];     // [2, EE] int32
    const float* w   = (const float*)d_in[2];   // [TE, 1] float32
    float* out = (float*)d_out;

    void *p_cnt, *p_tot, *p_xn, *p_x1;
    cudaGetSymbolAddress(&p_cnt, g_cnt);
    cudaGetSymbolAddress(&p_tot, g_total);
    cudaGetSymbolAddress(&p_xn,  g_xn);
    cudaGetSymbolAddress(&p_x1,  g_x1);

    const int THR = 256;

    // CSR build: degrees -> bucket alloc -> fill
    cudaMemsetAsync(p_cnt, 0, NN * sizeof(int));
    cudaMemsetAsync(p_tot, 0, sizeof(int));
    k_count<<<(TE + THR - 1) / THR, THR>>>(ei);
    k_build_off<<<NBLK, THR>>>();
    k_fill<<<(TE + THR - 1) / THR, THR>>>(ei, w);

    // x = l2norm(emb)
    k_norm<<<(NN + 15) / 16, THR>>>(emb);

    // layer 1: x1 = leaky(gather(xn)/deg)            (fused epilogue)
    k_gather<false><<<(NN + 7) / 8, THR>>>((const float*)p_xn, (float*)p_x1);
    // layer 2: out = xn + x1 + leaky(gather(x1)/deg) (fused epilogue)
    k_gather<true><<<(NN + 7) / 8, THR>>>((const float*)p_x1, out);
}